// round 1
// baseline (speedup 1.0000x reference)
#include <cuda_runtime.h>
#include <cstdint>

// Conv2d: N=32, C_IN=3, H=W=224, C_OUT=64, K=3, stride=1, pad=1, fp32.
// Strategy: direct conv, packed fp32x2 FMA (Blackwell fma.rn.f32x2).
// Each thread: 4 consecutive x outputs (2 f32x2 pairs) x 32 output channels.
// Channel half selected by gridDim.z (z = n*2 + half).
// Weights duplicated (w,w) into shared memory -> LDS.64 broadcast, each
// weight feeds 2 FMA2s so the fma pipe (rt=2/SMSP) is the binding resource.

#define NN 32
#define CIN 3
#define HH 224
#define WW 224
#define COUT 64
#define CO_PER 32   // channels per thread (half of COUT)
#define TX 4        // x-pixels per thread
#define BX 56       // threads in x (56*4 = 224)
#define BY 2        // rows per block
#define NTHREADS (BX*BY)

typedef unsigned long long ull;

__device__ __forceinline__ ull pk2(float lo, float hi) {
    ull r;
    asm("mov.b64 %0, {%1, %2};" : "=l"(r) : "f"(lo), "f"(hi));
    return r;
}
__device__ __forceinline__ void fma2(ull& d, ull a, ull b) {
    asm("fma.rn.f32x2 %0, %1, %2, %0;" : "+l"(d) : "l"(a), "l"(b));
}
__device__ __forceinline__ void unpk2(ull v, float& lo, float& hi) {
    asm("mov.b64 {%0, %1}, %2;" : "=f"(lo), "=f"(hi) : "l"(v));
}

__global__ __launch_bounds__(NTHREADS, 1)
void conv3x3_kernel(const float* __restrict__ x_in,
                    const float* __restrict__ weight,
                    const float* __restrict__ bias,
                    float* __restrict__ out)
{
    __shared__ float2 s_w[CO_PER * 27];   // duplicated (w,w), [co][ci][ky][kx]

    const int tx  = threadIdx.x;          // 0..55
    const int ty  = threadIdx.y;          // 0..BY-1
    const int tid = ty * BX + tx;

    const int z    = blockIdx.z;          // n*2 + half
    const int n    = z >> 1;
    const int half = z & 1;
    const int y    = blockIdx.y * BY + ty;    // 0..223
    const int x0   = tx * TX;                 // 0..220, multiple of 4

    // Stage duplicated weights for this channel half into shared.
    for (int i = tid; i < CO_PER * 27; i += NTHREADS) {
        const int co  = i / 27;
        const int rem = i % 27;
        const float w = weight[(half * CO_PER + co) * 27 + rem];
        s_w[i] = make_float2(w, w);
    }
    __syncthreads();

    // Accumulators: 32 channels x 2 packed pairs (outputs x0..x0+3).
    ull acc[CO_PER][2];
#pragma unroll
    for (int co = 0; co < CO_PER; ++co) {
        const float b = __ldg(&bias[half * CO_PER + co]);
        const ull bp = pk2(b, b);
        acc[co][0] = bp;
        acc[co][1] = bp;
    }

    const float* in_n = x_in + (size_t)n * CIN * HH * WW;

#pragma unroll 1
    for (int ci = 0; ci < CIN; ++ci) {
        const float* in_c = in_n + (size_t)ci * HH * WW;
#pragma unroll 1
        for (int ky = 0; ky < 3; ++ky) {
            const int yy = y + ky - 1;
            const bool rowok = ((unsigned)yy < (unsigned)HH);
            const float* row = in_c + yy * WW;

            // 6 input scalars covering x0-1 .. x0+4 (zero-padded at edges)
            float r[6];
#pragma unroll
            for (int j = 0; j < 6; ++j) {
                const int xx = x0 - 1 + j;
                r[j] = (rowok && (unsigned)xx < (unsigned)WW) ? __ldg(row + xx) : 0.0f;
            }
            // packed input pairs: p[k] = (r[k], r[k+1])
            ull p[5];
#pragma unroll
            for (int j = 0; j < 5; ++j) p[j] = pk2(r[j], r[j + 1]);

            const int wbase = ci * 9 + ky * 3;
#pragma unroll
            for (int co = 0; co < CO_PER; ++co) {
#pragma unroll
                for (int kx = 0; kx < 3; ++kx) {
                    const ull wv = *reinterpret_cast<const ull*>(&s_w[co * 27 + wbase + kx]);
                    fma2(acc[co][0], p[kx],     wv);   // outputs (x0,   x0+1)
                    fma2(acc[co][1], p[kx + 2], wv);   // outputs (x0+2, x0+3)
                }
            }
        }
    }

    // Store: 32 channels x float4 (coalesced, 16B aligned since x0 % 4 == 0)
    const size_t out_nbase = ((size_t)n * COUT + half * CO_PER) * (HH * WW)
                           + (size_t)y * WW + x0;
#pragma unroll
    for (int co = 0; co < CO_PER; ++co) {
        float4 v;
        unpk2(acc[co][0], v.x, v.y);
        unpk2(acc[co][1], v.z, v.w);
        *reinterpret_cast<float4*>(out + out_nbase + (size_t)co * (HH * WW)) = v;
    }
}

extern "C" void kernel_launch(void* const* d_in, const int* in_sizes, int n_in,
                              void* d_out, int out_size)
{
    const float* x = (const float*)d_in[0];
    const float* w = (const float*)d_in[1];
    const float* b = (const float*)d_in[2];
    float* out = (float*)d_out;

    dim3 block(BX, BY, 1);                 // 112 threads
    dim3 grid(1, HH / BY, NN * 2);         // (1, 112, 64)
    conv3x3_kernel<<<grid, block>>>(x, w, b, out);
}

// round 2
// speedup vs baseline: 1.1266x; 1.1266x over previous
#include <cuda_runtime.h>
#include <cstdint>

// Conv2d: N=32, C_IN=3, H=W=224, C_OUT=64, K=3, stride=1, pad=1, fp32.
// Direct conv with packed fp32x2 FMA.
// Each thread: 8 consecutive x outputs (4 f32x2 pairs) x 8 output channels.
// Channel octant selected via blockIdx.z (z = n*8 + chunk).
// Weights duplicated (w,w) in shared -> each LDS.64 feeds 4 FMA2s.

#define NN 32
#define CIN 3
#define HH 224
#define WW 224
#define COUT 64
#define CO_PER 8     // channels per thread (1/8 of COUT)
#define TX 8         // x-pixels per thread
#define TPR (WW/TX)  // 28 threads per row
#define ROWS 8       // rows per block
#define NTHREADS (TPR*ROWS)   // 224

typedef unsigned long long ull;

__device__ __forceinline__ ull pk2(float lo, float hi) {
    ull r;
    asm("mov.b64 %0, {%1, %2};" : "=l"(r) : "f"(lo), "f"(hi));
    return r;
}
__device__ __forceinline__ void fma2(ull& d, ull a, ull b) {
    asm("fma.rn.f32x2 %0, %1, %2, %0;" : "+l"(d) : "l"(a), "l"(b));
}
__device__ __forceinline__ void unpk2(ull v, float& lo, float& hi) {
    asm("mov.b64 {%0, %1}, %2;" : "=f"(lo), "=f"(hi) : "l"(v));
}

__global__ __launch_bounds__(NTHREADS, 2)
void conv3x3_kernel(const float* __restrict__ x_in,
                    const float* __restrict__ weight,
                    const float* __restrict__ bias,
                    float* __restrict__ out)
{
    __shared__ float2 s_w[CO_PER * 27];   // duplicated (w,w), [co][ci*9+ky*3+kx]

    const int tid  = threadIdx.x;          // 0..223
    const int txc  = tid % TPR;            // x-chunk 0..27
    const int trow = tid / TPR;            // 0..7

    const int z     = blockIdx.z;          // n*8 + chunk
    const int n     = z >> 3;
    const int chunk = z & 7;
    const int y     = blockIdx.y * ROWS + trow;   // 0..223
    const int x0    = txc * TX;                    // multiple of 8

    // Stage duplicated weights for this channel octant (8*27 = 216 <= 224 threads).
    if (tid < CO_PER * 27) {
        const int co  = tid / 27;
        const int rem = tid % 27;
        const float w = weight[(chunk * CO_PER + co) * 27 + rem];
        s_w[tid] = make_float2(w, w);
    }
    __syncthreads();

    // Accumulators: 8 channels x 4 packed pairs (outputs x0..x0+7) = 64 regs.
    ull acc[CO_PER][4];
#pragma unroll
    for (int co = 0; co < CO_PER; ++co) {
        const float b = __ldg(&bias[chunk * CO_PER + co]);
        const ull bp = pk2(b, b);
#pragma unroll
        for (int j = 0; j < 4; ++j) acc[co][j] = bp;
    }

    const bool left  = (x0 == 0);
    const bool right = (x0 + TX == WW);
    const float* in_n = x_in + (size_t)n * CIN * HH * WW;

#pragma unroll 1
    for (int ci = 0; ci < CIN; ++ci) {
        const float* in_c = in_n + (size_t)ci * HH * WW;
#pragma unroll
        for (int ky = 0; ky < 3; ++ky) {
            const int yy = y + ky - 1;
            const bool rowok = ((unsigned)yy < (unsigned)HH);
            const float* row = in_c + yy * WW;

            // 10 input scalars covering x0-1 .. x0+8 (zero at pads).
            float r[10];
            if (rowok) {
                const float4 a = *reinterpret_cast<const float4*>(row + x0);
                const float4 b = *reinterpret_cast<const float4*>(row + x0 + 4);
                r[1] = a.x; r[2] = a.y; r[3] = a.z; r[4] = a.w;
                r[5] = b.x; r[6] = b.y; r[7] = b.z; r[8] = b.w;
                r[0] = left  ? 0.0f : __ldg(row + x0 - 1);
                r[9] = right ? 0.0f : __ldg(row + x0 + 8);
            } else {
#pragma unroll
                for (int j = 0; j < 10; ++j) r[j] = 0.0f;
            }
            // packed pairs p[i] = (r[i], r[i+1]) = inputs (x0-1+i, x0+i)
            ull p[9];
#pragma unroll
            for (int j = 0; j < 9; ++j) p[j] = pk2(r[j], r[j + 1]);

            const int wbase = ci * 9 + ky * 3;
#pragma unroll
            for (int co = 0; co < CO_PER; ++co) {
#pragma unroll
                for (int kx = 0; kx < 3; ++kx) {
                    const ull wv = *reinterpret_cast<const ull*>(&s_w[co * 27 + wbase + kx]);
                    fma2(acc[co][0], p[kx],     wv);   // outputs (x0,   x0+1)
                    fma2(acc[co][1], p[kx + 2], wv);   // outputs (x0+2, x0+3)
                    fma2(acc[co][2], p[kx + 4], wv);   // outputs (x0+4, x0+5)
                    fma2(acc[co][3], p[kx + 6], wv);   // outputs (x0+6, x0+7)
                }
            }
        }
    }

    // Store: 8 channels x 2 float4 (coalesced, 16B aligned).
    const size_t out_nbase = ((size_t)n * COUT + chunk * CO_PER) * (HH * WW)
                           + (size_t)y * WW + x0;
#pragma unroll
    for (int co = 0; co < CO_PER; ++co) {
        float4 v0, v1;
        unpk2(acc[co][0], v0.x, v0.y);
        unpk2(acc[co][1], v0.z, v0.w);
        unpk2(acc[co][2], v1.x, v1.y);
        unpk2(acc[co][3], v1.z, v1.w);
        float* o = out + out_nbase + (size_t)co * (HH * WW);
        *reinterpret_cast<float4*>(o)     = v0;
        *reinterpret_cast<float4*>(o + 4) = v1;
    }
}

extern "C" void kernel_launch(void* const* d_in, const int* in_sizes, int n_in,
                              void* d_out, int out_size)
{
    const float* x = (const float*)d_in[0];
    const float* w = (const float*)d_in[1];
    const float* b = (const float*)d_in[2];
    float* out = (float*)d_out;

    dim3 block(NTHREADS, 1, 1);            // 224 threads
    dim3 grid(1, HH / ROWS, NN * 8);       // (1, 28, 256)
    conv3x3_kernel<<<grid, block>>>(x, w, b, out);
}

// round 4
// speedup vs baseline: 2.0791x; 1.8454x over previous
#include <cuda_runtime.h>
#include <cstdint>

// Conv2d N=32, CIN=3, H=W=224, COUT=64, 3x3, s1, p1, fp32.
// Implicit GEMM on tensor cores via portable mma.sync.m16n8k16 (bf16 -> f32),
// fp32 emulated with 3 passes: xh*wh + xh*wl + xl*wh.
// Bias folded at k=27 (A=1.0, B=bias). K padded 27->32 (2 k-steps of 16).
// Per warp-tile: 16 pixels x 64 cout. No smem, no block syncs.

#define NN 32
#define HWDIM 224
#define IMG (HWDIM*HWDIM)        // 50176
#define COUT 64
#define CIN 3
#define NTHREADS 128
#define PX_PER_BLOCK 512
#define ITERS 8                  // 4 warps * 16 px * 8 = 512
#define BLKS_PER_IMG (IMG/PX_PER_BLOCK)   // 98

__device__ __forceinline__ uint32_t cvt_bf16x2(float hi, float lo) {
    uint32_t d;
    asm("cvt.rn.bf16x2.f32 %0, %1, %2;" : "=r"(d) : "f"(hi), "f"(lo));
    return d;
}
__device__ __forceinline__ void mma_bf16(float* d, const uint32_t* a, const uint32_t* b) {
    asm volatile(
        "mma.sync.aligned.m16n8k16.row.col.f32.bf16.bf16.f32 "
        "{%0,%1,%2,%3}, {%4,%5,%6,%7}, {%8,%9}, {%0,%1,%2,%3};"
        : "+f"(d[0]), "+f"(d[1]), "+f"(d[2]), "+f"(d[3])
        : "r"(a[0]), "r"(a[1]), "r"(a[2]), "r"(a[3]), "r"(b[0]), "r"(b[1]));
}

__global__ __launch_bounds__(NTHREADS, 3)
void conv_mma(const float* __restrict__ xin, const float* __restrict__ wgt,
              const float* __restrict__ bias, float* __restrict__ out)
{
    const int tid  = threadIdx.x;
    const int warp = tid >> 5;
    const int lane = tid & 31;
    const int lg   = lane >> 2;     // group 0..7 (pixel row / co within tile)
    const int c    = (lane & 3) * 2;

    const int n   = blockIdx.x / BLKS_PER_IMG;
    const int blk = blockIdx.x % BLKS_PER_IMG;
    const float* in_n  = xin + (size_t)n * (CIN * IMG);
    float*       out_n = out + (size_t)n * (COUT * IMG);

    // ---- B (weight+bias) fragments, hi/lo, built once per thread ----
    // B col-major 16x8: reg0 -> k=(c,c+1), reg1 -> k=(c+8,c+9); col co = nt*8+lg.
    uint32_t BH[8][2][2], BL[8][2][2];
#pragma unroll
    for (int nt = 0; nt < 8; ++nt) {
        const int co = nt * 8 + lg;
#pragma unroll
        for (int s = 0; s < 2; ++s)
#pragma unroll
        for (int r = 0; r < 2; ++r) {
            const int k0 = 16 * s + c + 8 * r;
            const int k1 = k0 + 1;
            const float f0 = (k0 < 27) ? wgt[co * 27 + k0] : (k0 == 27 ? bias[co] : 0.f);
            const float f1 = (k1 < 27) ? wgt[co * 27 + k1] : (k1 == 27 ? bias[co] : 0.f);
            const uint32_t h = cvt_bf16x2(f1, f0);
            const float l0 = f0 - __uint_as_float(h << 16);
            const float l1 = f1 - __uint_as_float(h & 0xffff0000u);
            BH[nt][s][r] = h;
            BL[nt][s][r] = cvt_bf16x2(l1, l0);
        }
    }

    // ---- tap descriptors for this lane's 8 k-slots: k = c + offs[t] ----
    const int offs[8] = {0, 1, 8, 9, 16, 17, 24, 25};
    int   coff[8], dy[8], dx[8];
    bool  valid[8];
    float fdef[8];                    // value when k>=27: 1.0 at k==27 (bias), else 0
#pragma unroll
    for (int t = 0; t < 8; ++t) {
        const int k = c + offs[t];
        valid[t] = (k < 27);
        const int kk = valid[t] ? k : 0;
        const int ci = kk / 9, r = kk % 9;
        coff[t] = ci * IMG;
        dy[t]   = r / 3 - 1;
        dx[t]   = r % 3 - 1;
        fdef[t] = (k == 27) ? 1.f : 0.f;
    }

    for (int it = 0; it < ITERS; ++it) {
        const int p0 = blk * PX_PER_BLOCK + it * 64 + warp * 16 + lg;  // rows 0-7
        const int p1 = p0 + 8;                                          // rows 8-15
        const int y  = p0 / HWDIM;       // p0,p1 share the row (16 | 224)
        const int x0 = p0 % HWDIM;

        // ---- gather 8 taps for both pixels ----
        float v0[8], v1[8];
#pragma unroll
        for (int t = 0; t < 8; ++t) {
            const int  yy    = y + dy[t];
            const bool rowok = valid[t] && ((unsigned)yy < (unsigned)HWDIM);
            const float* rp  = in_n + coff[t] + yy * HWDIM;
            const int  xx0   = x0 + dx[t];
            const bool ok0   = rowok && ((unsigned)xx0 < (unsigned)HWDIM);
            const bool ok1   = rowok && (xx0 + 8 < HWDIM);
            const float dflt = valid[t] ? 0.f : fdef[t];
            v0[t] = ok0 ? __ldg(rp + xx0)     : dflt;
            v1[t] = ok1 ? __ldg(rp + xx0 + 8) : dflt;
        }

        // ---- split hi/lo, pack A fragments ----
        // A row-major 16x16: regs {p0 klow, p1 klow, p0 khigh, p1 khigh}
        uint32_t AH[2][4], AL[2][4];
#pragma unroll
        for (int s = 0; s < 2; ++s)
#pragma unroll
        for (int r = 0; r < 2; ++r) {
            const int t0 = 4 * s + 2 * r;
            const float f00 = v0[t0], f01 = v0[t0 + 1];
            const float f10 = v1[t0], f11 = v1[t0 + 1];
            const uint32_t h0 = cvt_bf16x2(f01, f00);
            const uint32_t h1 = cvt_bf16x2(f11, f10);
            AH[s][2 * r]     = h0;
            AH[s][2 * r + 1] = h1;
            const float l00 = f00 - __uint_as_float(h0 << 16);
            const float l01 = f01 - __uint_as_float(h0 & 0xffff0000u);
            const float l10 = f10 - __uint_as_float(h1 << 16);
            const float l11 = f11 - __uint_as_float(h1 & 0xffff0000u);
            AL[s][2 * r]     = cvt_bf16x2(l01, l00);
            AL[s][2 * r + 1] = cvt_bf16x2(l11, l10);
        }

        // ---- 48 MMAs: 8 n-tiles x 2 k-steps x 3 passes ----
        float acc[8][4];
#pragma unroll
        for (int nt = 0; nt < 8; ++nt) {
            acc[nt][0] = 0.f; acc[nt][1] = 0.f; acc[nt][2] = 0.f; acc[nt][3] = 0.f;
        }
#pragma unroll
        for (int nt = 0; nt < 8; ++nt) {
#pragma unroll
            for (int s = 0; s < 2; ++s) {
                mma_bf16(acc[nt], AH[s], BH[nt][s]);
                mma_bf16(acc[nt], AH[s], BL[nt][s]);
                mma_bf16(acc[nt], AL[s], BH[nt][s]);
            }
        }

        // ---- store: D c0->(co,p0) c1->(co+1,p0) c2->(co,p1) c3->(co+1,p1) ----
#pragma unroll
        for (int nt = 0; nt < 8; ++nt) {
            const int co = nt * 8 + c;
            float* pl0 = out_n + (size_t)co * IMG;
            float* pl1 = pl0 + IMG;
            pl0[p0] = acc[nt][0];
            pl1[p0] = acc[nt][1];
            pl0[p1] = acc[nt][2];
            pl1[p1] = acc[nt][3];
        }
    }
}

extern "C" void kernel_launch(void* const* d_in, const int* in_sizes, int n_in,
                              void* d_out, int out_size)
{
    const float* x = (const float*)d_in[0];
    const float* w = (const float*)d_in[1];
    const float* b = (const float*)d_in[2];
    float* out = (float*)d_out;

    dim3 block(NTHREADS, 1, 1);
    dim3 grid(NN * BLKS_PER_IMG, 1, 1);   // 32*98 = 3136
    conv_mma<<<grid, block>>>(x, w, b, out);
}